// round 1
// baseline (speedup 1.0000x reference)
#include <cuda_runtime.h>
#include <math.h>

// Problem constants
#define NB  4
#define NT  2048
#define NC  1024
#define NHH 16
#define HD  64

// Device-global scratch (allocation-free rule: no cudaMalloc allowed)
__device__ float g_q[(size_t)NB * NHH * NT * HD];   // [B,NH,T,HD] 32MB
__device__ float g_k[(size_t)NB * NHH * NT * HD];
__device__ float g_v[(size_t)NB * NHH * NT * HD];
__device__ float g_y[(size_t)NB * NT * NC];         // attention output [B,T,C]

// ---------------------------------------------------------------------------
// GEMM 1: qkv = x @ w_attn + b_attn, scattered to head-major q/k/v
// A [8192,1024] row-major, W [1024,3072] row-major. BM=BN=64, BK=16, 4x4/thread.
// ---------------------------------------------------------------------------
__global__ __launch_bounds__(256) void gemm_qkv_kernel(
    const float* __restrict__ A, const float* __restrict__ W,
    const float* __restrict__ bias)
{
    __shared__ float As[16][64];   // [k][m] (transposed)
    __shared__ float Bs[16][64];   // [k][n]
    const int tid = threadIdx.x;
    const int tx = tid & 15, ty = tid >> 4;
    const int m0 = blockIdx.y * 64, n0 = blockIdx.x * 64;
    const int K = NC, N = 3 * NC;

    float acc[4][4] = {};
    const int arow = tid >> 2,  acol = (tid & 3) << 2;
    const int brow = tid >> 4,  bcol = (tid & 15) << 2;
    const float* Ap = A + (size_t)(m0 + arow) * K + acol;
    const float* Wp = W + (size_t)brow * N + n0 + bcol;

    for (int k0 = 0; k0 < K; k0 += 16) {
        float4 a4 = *(const float4*)(Ap + k0);
        As[acol + 0][arow] = a4.x; As[acol + 1][arow] = a4.y;
        As[acol + 2][arow] = a4.z; As[acol + 3][arow] = a4.w;
        *(float4*)(&Bs[brow][bcol]) = *(const float4*)(Wp + (size_t)k0 * N);
        __syncthreads();
#pragma unroll
        for (int kk = 0; kk < 16; kk++) {
            float4 av = *(const float4*)(&As[kk][ty << 2]);
            float4 bv = *(const float4*)(&Bs[kk][tx << 2]);
            float af[4] = {av.x, av.y, av.z, av.w};
            float bf[4] = {bv.x, bv.y, bv.z, bv.w};
#pragma unroll
            for (int i = 0; i < 4; i++)
#pragma unroll
                for (int j = 0; j < 4; j++) acc[i][j] += af[i] * bf[j];
        }
        __syncthreads();
    }

    // Epilogue: tile is 64 cols wide & 64-aligned -> one (which, head) per block
    const int which = n0 >> 10;                 // 0=q, 1=k, 2=v
    float* dst = (which == 0) ? g_q : (which == 1) ? g_k : g_v;
    const int h = (n0 & (NC - 1)) >> 6;
#pragma unroll
    for (int i = 0; i < 4; i++) {
        int m = m0 + (ty << 2) + i;
        int b = m >> 11, t = m & (NT - 1);
        float* row = dst + ((size_t)(b * NHH + h) * NT + t) * HD;
#pragma unroll
        for (int j = 0; j < 4; j++) {
            int d = (tx << 2) + j;
            row[d] = acc[i][j] + bias[n0 + d];
        }
    }
}

// ---------------------------------------------------------------------------
// Flash attention, causal. One block = one (b,h) x 64-query tile.
// Smem: Q^T[d][r], K^T[d][c] (reused as P^T[c][r]), V[c][d] = exactly 48KB.
// Online softmax stats (m,l,scale) live in registers: each thread owns the
// same 4 rows in S and O, and the 16 row-group threads hold identical values
// after the 16-lane butterfly reductions.
// ---------------------------------------------------------------------------
__global__ __launch_bounds__(256) void flash_kernel()
{
    __shared__ float Qts[64 * 64];   // [d][r]
    __shared__ float KPs[64 * 64];   // K^T [d][c], then P^T [c][r]
    __shared__ float Vs [64 * 64];   // [c][d]

    const int tid = threadIdx.x;
    const int tx = tid & 15, ty = tid >> 4;
    const int qi = blockIdx.x, bh = blockIdx.y;
    const int q0 = qi * 64;

    const float* Qg = g_q + (size_t)bh * NT * HD;
    const float* Kg = g_k + (size_t)bh * NT * HD;
    const float* Vg = g_v + (size_t)bh * NT * HD;

    // Load Q tile transposed
#pragma unroll
    for (int it = 0; it < 4; it++) {
        int f   = tid + it * 256;        // float4 index within 64x64 tile
        int row = f >> 4;
        int col = (f & 15) << 2;
        float4 v = *(const float4*)(Qg + (size_t)(q0 + row) * HD + col);
        Qts[(col + 0) * 64 + row] = v.x; Qts[(col + 1) * 64 + row] = v.y;
        Qts[(col + 2) * 64 + row] = v.z; Qts[(col + 3) * 64 + row] = v.w;
    }

    float m_i[4], l_i[4], acc[4][4] = {};
#pragma unroll
    for (int i = 0; i < 4; i++) { m_i[i] = -1e30f; l_i[i] = 0.f; }

    for (int kt = 0; kt <= qi; kt++) {
        const int k0 = kt * 64;
        __syncthreads();   // prev PV reads of KPs/Vs done (also covers Q load, 1st iter)
#pragma unroll
        for (int it = 0; it < 4; it++) {
            int f   = tid + it * 256;
            int row = f >> 4;
            int col = (f & 15) << 2;
            float4 kv = *(const float4*)(Kg + (size_t)(k0 + row) * HD + col);
            KPs[(col + 0) * 64 + row] = kv.x; KPs[(col + 1) * 64 + row] = kv.y;
            KPs[(col + 2) * 64 + row] = kv.z; KPs[(col + 3) * 64 + row] = kv.w;
            *(float4*)(&Vs[row * 64 + col]) =
                *(const float4*)(Vg + (size_t)(k0 + row) * HD + col);
        }
        __syncthreads();

        // S = Q K^T  (64x64x64, 4x4 per thread)
        float s[4][4] = {};
#pragma unroll 8
        for (int d = 0; d < 64; d++) {
            float4 qv = *(const float4*)(&Qts[d * 64 + (ty << 2)]);
            float4 kv = *(const float4*)(&KPs[d * 64 + (tx << 2)]);
            float qf[4] = {qv.x, qv.y, qv.z, qv.w};
            float kf[4] = {kv.x, kv.y, kv.z, kv.w};
#pragma unroll
            for (int i = 0; i < 4; i++)
#pragma unroll
                for (int j = 0; j < 4; j++) s[i][j] += qf[i] * kf[j];
        }

        // scale + causal mask (diagonal tile only)
        const bool diag = (kt == qi);
#pragma unroll
        for (int i = 0; i < 4; i++)
#pragma unroll
            for (int j = 0; j < 4; j++) {
                float v = s[i][j] * 0.125f;   // 1/sqrt(64)
                if (diag && ((tx << 2) + j) > ((ty << 2) + i)) v = -1e30f;
                s[i][j] = v;
            }

        // online softmax: per-row reductions over the 16-thread row group
        float sc[4];
#pragma unroll
        for (int i = 0; i < 4; i++) {
            float r = fmaxf(fmaxf(s[i][0], s[i][1]), fmaxf(s[i][2], s[i][3]));
#pragma unroll
            for (int o = 8; o >= 1; o >>= 1)
                r = fmaxf(r, __shfl_xor_sync(0xffffffffu, r, o));
            float m_new = fmaxf(m_i[i], r);
            float sum = 0.f;
#pragma unroll
            for (int j = 0; j < 4; j++) {
                float p = __expf(s[i][j] - m_new);
                s[i][j] = p;
                sum += p;
            }
#pragma unroll
            for (int o = 8; o >= 1; o >>= 1)
                sum += __shfl_xor_sync(0xffffffffu, sum, o);
            sc[i]  = __expf(m_i[i] - m_new);
            l_i[i] = l_i[i] * sc[i] + sum;
            m_i[i] = m_new;
        }

        __syncthreads();   // everyone done reading K^T from KPs
        // write P transposed [c][r] into KPs
#pragma unroll
        for (int j = 0; j < 4; j++)
#pragma unroll
            for (int i = 0; i < 4; i++)
                KPs[((tx << 2) + j) * 64 + (ty << 2) + i] = s[i][j];
        __syncthreads();

        // O = O*scale + P V
#pragma unroll
        for (int i = 0; i < 4; i++)
#pragma unroll
            for (int j = 0; j < 4; j++) acc[i][j] *= sc[i];
#pragma unroll 8
        for (int c = 0; c < 64; c++) {
            float4 pv = *(const float4*)(&KPs[c * 64 + (ty << 2)]);
            float4 vv = *(const float4*)(&Vs [c * 64 + (tx << 2)]);
            float pf[4] = {pv.x, pv.y, pv.z, pv.w};
            float vf[4] = {vv.x, vv.y, vv.z, vv.w};
#pragma unroll
            for (int i = 0; i < 4; i++)
#pragma unroll
                for (int j = 0; j < 4; j++) acc[i][j] += pf[i] * vf[j];
        }
    }

    // epilogue: O / l -> g_y [B,T,C] with head offset
    const int b = bh >> 4, h = bh & 15;
#pragma unroll
    for (int i = 0; i < 4; i++) {
        float inv = 1.f / l_i[i];
        int t = q0 + (ty << 2) + i;
        float* orow = g_y + (size_t)(b * NT + t) * NC + h * HD;
#pragma unroll
        for (int j = 0; j < 4; j++)
            orow[(tx << 2) + j] = acc[i][j] * inv;
    }
}

// ---------------------------------------------------------------------------
// GEMM 2: out = y @ w_proj + b_proj. A = g_y [8192,1024], W [1024,1024].
// ---------------------------------------------------------------------------
__global__ __launch_bounds__(256) void gemm_proj_kernel(
    const float* __restrict__ W, const float* __restrict__ bias,
    float* __restrict__ out)
{
    __shared__ float As[16][64];
    __shared__ float Bs[16][64];
    const int tid = threadIdx.x;
    const int tx = tid & 15, ty = tid >> 4;
    const int m0 = blockIdx.y * 64, n0 = blockIdx.x * 64;
    const int K = NC, N = NC;

    float acc[4][4] = {};
    const int arow = tid >> 2,  acol = (tid & 3) << 2;
    const int brow = tid >> 4,  bcol = (tid & 15) << 2;
    const float* Ap = g_y + (size_t)(m0 + arow) * K + acol;
    const float* Wp = W + (size_t)brow * N + n0 + bcol;

    for (int k0 = 0; k0 < K; k0 += 16) {
        float4 a4 = *(const float4*)(Ap + k0);
        As[acol + 0][arow] = a4.x; As[acol + 1][arow] = a4.y;
        As[acol + 2][arow] = a4.z; As[acol + 3][arow] = a4.w;
        *(float4*)(&Bs[brow][bcol]) = *(const float4*)(Wp + (size_t)k0 * N);
        __syncthreads();
#pragma unroll
        for (int kk = 0; kk < 16; kk++) {
            float4 av = *(const float4*)(&As[kk][ty << 2]);
            float4 bv = *(const float4*)(&Bs[kk][tx << 2]);
            float af[4] = {av.x, av.y, av.z, av.w};
            float bf[4] = {bv.x, bv.y, bv.z, bv.w};
#pragma unroll
            for (int i = 0; i < 4; i++)
#pragma unroll
                for (int j = 0; j < 4; j++) acc[i][j] += af[i] * bf[j];
        }
        __syncthreads();
    }
#pragma unroll
    for (int i = 0; i < 4; i++) {
        int m = m0 + (ty << 2) + i;
#pragma unroll
        for (int j = 0; j < 4; j++) {
            int n = n0 + (tx << 2) + j;
            out[(size_t)m * N + n] = acc[i][j] + bias[n];
        }
    }
}

// ---------------------------------------------------------------------------
extern "C" void kernel_launch(void* const* d_in, const int* in_sizes, int n_in,
                              void* d_out, int out_size)
{
    const float* x      = (const float*)d_in[0];
    const float* w_attn = (const float*)d_in[1];
    const float* b_attn = (const float*)d_in[2];
    const float* w_proj = (const float*)d_in[3];
    const float* b_proj = (const float*)d_in[4];
    float* out = (float*)d_out;

    dim3 g1(3 * NC / 64, (NB * NT) / 64);   // (48,128)
    gemm_qkv_kernel<<<g1, 256>>>(x, w_attn, b_attn);

    dim3 g2(NT / 64, NB * NHH);             // (32,64)
    flash_kernel<<<g2, 256>>>();

    dim3 g3(NC / 64, (NB * NT) / 64);       // (16,128)
    gemm_proj_kernel<<<g3, 256>>>(w_proj, b_proj, out);
}

// round 4
// speedup vs baseline: 1.4579x; 1.4579x over previous
#include <cuda_runtime.h>
#include <cuda_bf16.h>
#include <cstdint>
#include <math.h>

#define NB  4
#define NT  2048
#define NC  1024
#define NHH 16
#define HD  64

// Device-global scratch (no cudaMalloc allowed)
__device__ float g_q[(size_t)NB * NHH * NT * HD];
__device__ float g_k[(size_t)NB * NHH * NT * HD];
__device__ float g_v[(size_t)NB * NHH * NT * HD];
__device__ float g_y[(size_t)NB * NT * NC];

// ============================ helpers ============================
__device__ __forceinline__ uint32_t pack_bf16(float a, float b) {
    // low 16 bits = a (lower k index), high = b
    __nv_bfloat162 t = __floats2bfloat162_rn(a, b);
    return *(uint32_t*)&t;
}
__device__ __forceinline__ void split2(float x, float& hi, float& lo) {
    __nv_bfloat16 h = __float2bfloat16(x);
    hi = __bfloat162float(h);
    lo = x - hi;
}
__device__ __forceinline__ void mma_bf16(float* d, const uint32_t* a, const uint32_t* b) {
    asm volatile(
        "mma.sync.aligned.m16n8k16.row.col.f32.bf16.bf16.f32 "
        "{%0,%1,%2,%3}, {%4,%5,%6,%7}, {%8,%9}, {%0,%1,%2,%3};"
        : "+f"(d[0]), "+f"(d[1]), "+f"(d[2]), "+f"(d[3])
        : "r"(a[0]), "r"(a[1]), "r"(a[2]), "r"(a[3]), "r"(b[0]), "r"(b[1]));
}

// ===================== bf16x3 split mma.sync GEMM =====================
// BM=128, BN=128, BK=32. 256 threads = 8 warps (2x4). Warp tile 64x32.
// Smem: A/B stored as b32 k-pairs (2 bf16), row pitch 20 b32 (conflict-free
// fragment reads: bank = g*20 + tq covers all 32 banks).
static constexpr int BM = 128, BN = 128, BK = 32;
static constexpr int KTOT = 1024, NCHUNK = KTOT / BK;
static constexpr int LDP = 20;   // row pitch in b32 (16 used + 4 pad)

// MODE 0: A = x, epilogue scatters to g_q/g_k/g_v with bias (NGLOB=3072)
// MODE 1: A = g_y, epilogue writes out + bias (NGLOB=1024)
template <int MODE, int NGLOB>
__global__ __launch_bounds__(256) void gemm_bf16_kernel(
    const float* __restrict__ A, const float* __restrict__ W,
    const float* __restrict__ bias, float* __restrict__ out)
{
    __shared__ uint32_t As_hi[BM * LDP];
    __shared__ uint32_t As_lo[BM * LDP];
    __shared__ uint32_t Bs_hi[BN * LDP];
    __shared__ uint32_t Bs_lo[BN * LDP];

    const int tid  = threadIdx.x;
    const int warp = tid >> 5, lane = tid & 31;
    const int g = lane >> 2, tq = lane & 3;        // fragment row group / pair idx
    const int wm = (warp >> 2) * 64;               // warp m offset (0/64)
    const int wn = (warp & 3) * 32;                // warp n offset
    const int m0 = blockIdx.y * BM, n0 = blockIdx.x * BN;
    const float* __restrict__ Ap = (MODE == 0) ? A : (const float*)g_y;

    // B staging assignment: thread covers n = tid&127, k-pairs pbase..pbase+7
    const int sn = tid & 127;
    const int pbase = (tid >> 7) * 8;

    float acc[4][4][4] = {};   // [fm][fn][frag reg]

    for (int ci = 0; ci < NCHUNK; ci++) {
        const int k0 = ci * BK;

        // ---- stage A [128 x 32] ----
#pragma unroll
        for (int it = 0; it < 4; it++) {
            int s = tid + it * 256;
            int row = s >> 3, q = s & 7;
            float4 v = *(const float4*)(Ap + (size_t)(m0 + row) * KTOT + k0 + q * 4);
            float h0, l0, h1, l1, h2, l2, h3, l3;
            split2(v.x, h0, l0); split2(v.y, h1, l1);
            split2(v.z, h2, l2); split2(v.w, h3, l3);
            int o = row * LDP + q * 2;
            As_hi[o]     = pack_bf16(h0, h1);
            As_hi[o + 1] = pack_bf16(h2, h3);
            As_lo[o]     = pack_bf16(l0, l1);
            As_lo[o + 1] = pack_bf16(l2, l3);
        }
        // ---- stage B: W[k0..k0+31][n0..n0+127] -> Bs[n][kpair] ----
        {
            const float* wp = W + (size_t)(k0 + pbase * 2) * NGLOB + n0 + sn;
#pragma unroll
            for (int j = 0; j < 8; j++) {
                float w0 = wp[0], w1 = wp[NGLOB];
                wp += 2 * (size_t)NGLOB;
                float h0, l0, h1, l1;
                split2(w0, h0, l0); split2(w1, h1, l1);
                Bs_hi[sn * LDP + pbase + j] = pack_bf16(h0, h1);
                Bs_lo[sn * LDP + pbase + j] = pack_bf16(l0, l1);
            }
        }
        __syncthreads();

        // ---- compute: 2 k16-steps, 4x4 fragment grid, 3 split passes ----
#pragma unroll
        for (int ks = 0; ks < 2; ks++) {
            const int pb = ks * 8 + tq;
            uint32_t ah[4][4], al[4][4];
#pragma unroll
            for (int fm = 0; fm < 4; fm++) {
                int r0 = (wm + fm * 16 + g) * LDP + pb;
                int r1 = r0 + 8 * LDP;
                ah[fm][0] = As_hi[r0];     ah[fm][1] = As_hi[r1];
                ah[fm][2] = As_hi[r0 + 4]; ah[fm][3] = As_hi[r1 + 4];
                al[fm][0] = As_lo[r0];     al[fm][1] = As_lo[r1];
                al[fm][2] = As_lo[r0 + 4]; al[fm][3] = As_lo[r1 + 4];
            }
            uint32_t bh[4][2], bl[4][2];
#pragma unroll
            for (int fn = 0; fn < 4; fn++) {
                int o = (wn + fn * 8 + g) * LDP + pb;
                bh[fn][0] = Bs_hi[o]; bh[fn][1] = Bs_hi[o + 4];
                bl[fn][0] = Bs_lo[o]; bl[fn][1] = Bs_lo[o + 4];
            }
#pragma unroll
            for (int fm = 0; fm < 4; fm++)
#pragma unroll
                for (int fn = 0; fn < 4; fn++) {
                    mma_bf16(acc[fm][fn], ah[fm], bl[fn]);   // hi*lo
                    mma_bf16(acc[fm][fn], al[fm], bh[fn]);   // lo*hi
                    mma_bf16(acc[fm][fn], ah[fm], bh[fn]);   // hi*hi
                }
        }
        __syncthreads();
    }

    // ---- epilogue ----
#pragma unroll
    for (int fm = 0; fm < 4; fm++) {
#pragma unroll
        for (int fn = 0; fn < 4; fn++) {
            int ng = n0 + wn + fn * 8 + tq * 2;
#pragma unroll
            for (int half = 0; half < 2; half++) {
                int m = m0 + wm + fm * 16 + g + half * 8;
                float v0 = acc[fm][fn][half * 2 + 0] + bias[ng];
                float v1 = acc[fm][fn][half * 2 + 1] + bias[ng + 1];
                if (MODE == 0) {
                    const int which = ng >> 10;
                    float* dst = (which == 0) ? g_q : (which == 1) ? g_k : g_v;
                    const int h = (ng & (NC - 1)) >> 6;
                    const int d = ng & (HD - 1);
                    float* p = dst + (((size_t)(m >> 11) * NHH + h) * NT + (m & (NT - 1))) * HD + d;
                    *(float2*)p = make_float2(v0, v1);
                } else {
                    *(float2*)(out + (size_t)m * NGLOB + ng) = make_float2(v0, v1);
                }
            }
        }
    }
}

// ===================== flash attention (verified scalar) =====================
__global__ __launch_bounds__(256) void flash_kernel()
{
    __shared__ float Qts[64 * 64];
    __shared__ float KPs[64 * 64];
    __shared__ float Vs [64 * 64];

    const int tid = threadIdx.x;
    const int tx = tid & 15, ty = tid >> 4;
    const int qi = blockIdx.x, bh = blockIdx.y;
    const int q0 = qi * 64;

    const float* Qg = g_q + (size_t)bh * NT * HD;
    const float* Kg = g_k + (size_t)bh * NT * HD;
    const float* Vg = g_v + (size_t)bh * NT * HD;

#pragma unroll
    for (int it = 0; it < 4; it++) {
        int f = tid + it * 256;
        int row = f >> 4;
        int col = (f & 15) << 2;
        float4 v = *(const float4*)(Qg + (size_t)(q0 + row) * HD + col);
        Qts[(col + 0) * 64 + row] = v.x; Qts[(col + 1) * 64 + row] = v.y;
        Qts[(col + 2) * 64 + row] = v.z; Qts[(col + 3) * 64 + row] = v.w;
    }

    float m_i[4], l_i[4], acc[4][4] = {};
#pragma unroll
    for (int i = 0; i < 4; i++) { m_i[i] = -1e30f; l_i[i] = 0.f; }

    for (int kt = 0; kt <= qi; kt++) {
        const int k0 = kt * 64;
        __syncthreads();
#pragma unroll
        for (int it = 0; it < 4; it++) {
            int f = tid + it * 256;
            int row = f >> 4;
            int col = (f & 15) << 2;
            float4 kv = *(const float4*)(Kg + (size_t)(k0 + row) * HD + col);
            KPs[(col + 0) * 64 + row] = kv.x; KPs[(col + 1) * 64 + row] = kv.y;
            KPs[(col + 2) * 64 + row] = kv.z; KPs[(col + 3) * 64 + row] = kv.w;
            *(float4*)(&Vs[row * 64 + col]) =
                *(const float4*)(Vg + (size_t)(k0 + row) * HD + col);
        }
        __syncthreads();

        float s[4][4] = {};
#pragma unroll 8
        for (int d = 0; d < 64; d++) {
            float4 qv = *(const float4*)(&Qts[d * 64 + (ty << 2)]);
            float4 kv = *(const float4*)(&KPs[d * 64 + (tx << 2)]);
            float qf[4] = {qv.x, qv.y, qv.z, qv.w};
            float kf[4] = {kv.x, kv.y, kv.z, kv.w};
#pragma unroll
            for (int i = 0; i < 4; i++)
#pragma unroll
                for (int j = 0; j < 4; j++) s[i][j] += qf[i] * kf[j];
        }

        const bool diag = (kt == qi);
#pragma unroll
        for (int i = 0; i < 4; i++)
#pragma unroll
            for (int j = 0; j < 4; j++) {
                float v = s[i][j] * 0.125f;
                if (diag && ((tx << 2) + j) > ((ty << 2) + i)) v = -1e30f;
                s[i][j] = v;
            }

        float sc[4];
#pragma unroll
        for (int i = 0; i < 4; i++) {
            float r = fmaxf(fmaxf(s[i][0], s[i][1]), fmaxf(s[i][2], s[i][3]));
#pragma unroll
            for (int o = 8; o >= 1; o >>= 1)
                r = fmaxf(r, __shfl_xor_sync(0xffffffffu, r, o));
            float m_new = fmaxf(m_i[i], r);
            float sum = 0.f;
#pragma unroll
            for (int j = 0; j < 4; j++) {
                float p = __expf(s[i][j] - m_new);
                s[i][j] = p;
                sum += p;
            }
#pragma unroll
            for (int o = 8; o >= 1; o >>= 1)
                sum += __shfl_xor_sync(0xffffffffu, sum, o);
            sc[i]  = __expf(m_i[i] - m_new);
            l_i[i] = l_i[i] * sc[i] + sum;
            m_i[i] = m_new;
        }

        __syncthreads();
#pragma unroll
        for (int j = 0; j < 4; j++)
#pragma unroll
            for (int i = 0; i < 4; i++)
                KPs[((tx << 2) + j) * 64 + (ty << 2) + i] = s[i][j];
        __syncthreads();

#pragma unroll
        for (int i = 0; i < 4; i++)
#pragma unroll
            for (int j = 0; j < 4; j++) acc[i][j] *= sc[i];
#pragma unroll 8
        for (int c = 0; c < 64; c++) {
            float4 pv = *(const float4*)(&KPs[c * 64 + (ty << 2)]);
            float4 vv = *(const float4*)(&Vs [c * 64 + (tx << 2)]);
            float pf[4] = {pv.x, pv.y, pv.z, pv.w};
            float vf[4] = {vv.x, vv.y, vv.z, vv.w};
#pragma unroll
            for (int i = 0; i < 4; i++)
#pragma unroll
                for (int j = 0; j < 4; j++) acc[i][j] += pf[i] * vf[j];
        }
    }

    const int b = bh >> 4, h = bh & 15;
#pragma unroll
    for (int i = 0; i < 4; i++) {
        float inv = 1.f / l_i[i];
        int t = q0 + (ty << 2) + i;
        float* orow = g_y + (size_t)(b * NT + t) * NC + h * HD;
#pragma unroll
        for (int j = 0; j < 4; j++)
            orow[(tx << 2) + j] = acc[i][j] * inv;
    }
}

// ===========================================================================
extern "C" void kernel_launch(void* const* d_in, const int* in_sizes, int n_in,
                              void* d_out, int out_size)
{
    const float* x      = (const float*)d_in[0];
    const float* w_attn = (const float*)d_in[1];
    const float* b_attn = (const float*)d_in[2];
    const float* w_proj = (const float*)d_in[3];
    const float* b_proj = (const float*)d_in[4];
    float* out = (float*)d_out;

    dim3 g1(3 * NC / BN, (NB * NT) / BM);   // (24, 64)
    gemm_bf16_kernel<0, 3 * NC><<<g1, 256>>>(x, w_attn, b_attn, nullptr);

    dim3 g2(NT / 64, NB * NHH);             // (32, 64)
    flash_kernel<<<g2, 256>>>();

    dim3 g3(NC / BN, (NB * NT) / BM);       // (8, 64)
    gemm_bf16_kernel<1, NC><<<g3, 256>>>(nullptr, w_proj, b_proj, out);
}

// round 6
// speedup vs baseline: 2.0998x; 1.4403x over previous
#include <cuda_runtime.h>
#include <cuda_bf16.h>
#include <cstdint>
#include <math.h>

#define NB  4
#define NT  2048
#define NC  1024
#define NHH 16
#define HD  64
#define HP  32   // HD/2 packed u32 per row

// Device-global scratch (no cudaMalloc allowed)
// Q/K/V stored pre-split as packed bf16 pairs (adjacent head-dim elems):
__device__ uint32_t g_qh[(size_t)NB * NHH * NT * HP];
__device__ uint32_t g_ql[(size_t)NB * NHH * NT * HP];
__device__ uint32_t g_kh[(size_t)NB * NHH * NT * HP];
__device__ uint32_t g_kl[(size_t)NB * NHH * NT * HP];
__device__ uint32_t g_vh[(size_t)NB * NHH * NT * HP];
__device__ uint32_t g_vl[(size_t)NB * NHH * NT * HP];
__device__ float    g_y [(size_t)NB * NT * NC];        // attention out (fp32)

// ============================ helpers ============================
__device__ __forceinline__ uint32_t pack_bf16(float a, float b) {
    __nv_bfloat162 t = __floats2bfloat162_rn(a, b);
    return *(uint32_t*)&t;
}
__device__ __forceinline__ void split2(float x, float& hi, float& lo) {
    __nv_bfloat16 h = __float2bfloat16(x);
    hi = __bfloat162float(h);
    lo = x - hi;
}
__device__ __forceinline__ void mma_bf16(float* d, const uint32_t* a, const uint32_t* b) {
    asm volatile(
        "mma.sync.aligned.m16n8k16.row.col.f32.bf16.bf16.f32 "
        "{%0,%1,%2,%3}, {%4,%5,%6,%7}, {%8,%9}, {%0,%1,%2,%3};"
        : "+f"(d[0]), "+f"(d[1]), "+f"(d[2]), "+f"(d[3])
        : "r"(a[0]), "r"(a[1]), "r"(a[2]), "r"(a[3]), "r"(b[0]), "r"(b[1]));
}

// ===================== bf16x3 split mma.sync GEMM =====================
static constexpr int BM = 128, BN = 128, BK = 32;
static constexpr int KTOT = 1024, NCHUNK = KTOT / BK;
static constexpr int LDP = 20;

// MODE 0: A = x, epilogue -> packed split g_q*/g_k*/g_v* with bias (NGLOB=3072)
// MODE 1: A = g_y, epilogue writes out + bias (NGLOB=1024)
template <int MODE, int NGLOB>
__global__ __launch_bounds__(256) void gemm_bf16_kernel(
    const float* __restrict__ A, const float* __restrict__ W,
    const float* __restrict__ bias, float* __restrict__ out)
{
    __shared__ uint32_t As_hi[BM * LDP];
    __shared__ uint32_t As_lo[BM * LDP];
    __shared__ uint32_t Bs_hi[BN * LDP];
    __shared__ uint32_t Bs_lo[BN * LDP];

    const int tid  = threadIdx.x;
    const int warp = tid >> 5, lane = tid & 31;
    const int g = lane >> 2, tq = lane & 3;
    const int wm = (warp >> 2) * 64;
    const int wn = (warp & 3) * 32;
    const int m0 = blockIdx.y * BM, n0 = blockIdx.x * BN;
    const float* __restrict__ Ap = (MODE == 0) ? A : (const float*)g_y;

    const int sn = tid & 127;
    const int pbase = (tid >> 7) * 8;

    float acc[4][4][4] = {};

    for (int ci = 0; ci < NCHUNK; ci++) {
        const int k0 = ci * BK;
#pragma unroll
        for (int it = 0; it < 4; it++) {
            int s = tid + it * 256;
            int row = s >> 3, q = s & 7;
            float4 v = *(const float4*)(Ap + (size_t)(m0 + row) * KTOT + k0 + q * 4);
            float h0, l0, h1, l1, h2, l2, h3, l3;
            split2(v.x, h0, l0); split2(v.y, h1, l1);
            split2(v.z, h2, l2); split2(v.w, h3, l3);
            int o = row * LDP + q * 2;
            As_hi[o]     = pack_bf16(h0, h1);
            As_hi[o + 1] = pack_bf16(h2, h3);
            As_lo[o]     = pack_bf16(l0, l1);
            As_lo[o + 1] = pack_bf16(l2, l3);
        }
        {
            const float* wp = W + (size_t)(k0 + pbase * 2) * NGLOB + n0 + sn;
#pragma unroll
            for (int j = 0; j < 8; j++) {
                float w0 = wp[0], w1 = wp[NGLOB];
                wp += 2 * (size_t)NGLOB;
                float h0, l0, h1, l1;
                split2(w0, h0, l0); split2(w1, h1, l1);
                Bs_hi[sn * LDP + pbase + j] = pack_bf16(h0, h1);
                Bs_lo[sn * LDP + pbase + j] = pack_bf16(l0, l1);
            }
        }
        __syncthreads();

#pragma unroll
        for (int ks = 0; ks < 2; ks++) {
            const int pb = ks * 8 + tq;
            uint32_t ah[4][4], al[4][4];
#pragma unroll
            for (int fm = 0; fm < 4; fm++) {
                int r0 = (wm + fm * 16 + g) * LDP + pb;
                int r1 = r0 + 8 * LDP;
                ah[fm][0] = As_hi[r0];     ah[fm][1] = As_hi[r1];
                ah[fm][2] = As_hi[r0 + 4]; ah[fm][3] = As_hi[r1 + 4];
                al[fm][0] = As_lo[r0];     al[fm][1] = As_lo[r1];
                al[fm][2] = As_lo[r0 + 4]; al[fm][3] = As_lo[r1 + 4];
            }
            uint32_t bh[4][2], bl[4][2];
#pragma unroll
            for (int fn = 0; fn < 4; fn++) {
                int o = (wn + fn * 8 + g) * LDP + pb;
                bh[fn][0] = Bs_hi[o]; bh[fn][1] = Bs_hi[o + 4];
                bl[fn][0] = Bs_lo[o]; bl[fn][1] = Bs_lo[o + 4];
            }
#pragma unroll
            for (int fm = 0; fm < 4; fm++)
#pragma unroll
                for (int fn = 0; fn < 4; fn++) {
                    mma_bf16(acc[fm][fn], ah[fm], bl[fn]);
                    mma_bf16(acc[fm][fn], al[fm], bh[fn]);
                    mma_bf16(acc[fm][fn], ah[fm], bh[fn]);
                }
        }
        __syncthreads();
    }

    // ---- epilogue ----
#pragma unroll
    for (int fm = 0; fm < 4; fm++) {
#pragma unroll
        for (int fn = 0; fn < 4; fn++) {
            int ng = n0 + wn + fn * 8 + tq * 2;
#pragma unroll
            for (int half = 0; half < 2; half++) {
                int m = m0 + wm + fm * 16 + g + half * 8;
                float v0 = acc[fm][fn][half * 2 + 0] + bias[ng];
                float v1 = acc[fm][fn][half * 2 + 1] + bias[ng + 1];
                if (MODE == 0) {
                    const int which = ng >> 10;
                    const int h = (ng & (NC - 1)) >> 6;
                    const int d = ng & (HD - 1);
                    float h0, l0, h1, l1;
                    split2(v0, h0, l0); split2(v1, h1, l1);
                    size_t idx = (((size_t)(m >> 11) * NHH + h) * NT + (m & (NT - 1))) * HP + (d >> 1);
                    uint32_t* dh = (which == 0) ? g_qh : (which == 1) ? g_kh : g_vh;
                    uint32_t* dl = (which == 0) ? g_ql : (which == 1) ? g_kl : g_vl;
                    dh[idx] = pack_bf16(h0, h1);
                    dl[idx] = pack_bf16(l0, l1);
                } else {
                    *(float2*)(out + (size_t)m * NGLOB + ng) = make_float2(v0, v1);
                }
            }
        }
    }
}

// ===================== flash attention, mma.sync bf16x3 =====================
// Block: 8 warps = 128 query rows. Warp w owns rows q0+16w .. +15.
// K tiles of 64 keys. S fragments reused in-register as P operand of PV.
static constexpr int FP = 36;   // smem pitch (u32): (4g+tq) mod 32 conflict-free

__global__ __launch_bounds__(256) void flash_mma_kernel()
{
    __shared__ uint32_t Ksh[64 * FP];
    __shared__ uint32_t Ksl[64 * FP];
    __shared__ uint32_t Vth[64 * FP];   // V transposed: [hd][key-pair]
    __shared__ uint32_t Vtl[64 * FP];

    const int tid  = threadIdx.x;
    const int warp = tid >> 5, lane = tid & 31;
    const int g = lane >> 2, tq = lane & 3;
    const int qi = blockIdx.x, bh = blockIdx.y;
    const int q0 = qi * 128;
    const int rw = q0 + warp * 16 + g;          // this thread's first row

    const size_t base = (size_t)bh * NT * HP;
    const uint32_t* __restrict__ qh = g_qh + base;
    const uint32_t* __restrict__ ql = g_ql + base;
    const uint32_t* __restrict__ kh = g_kh + base;
    const uint32_t* __restrict__ kl = g_kl + base;
    const uint32_t* __restrict__ vh = g_vh + base;
    const uint32_t* __restrict__ vl = g_vl + base;

    // Q fragments for the whole kernel (rows rw, rw+8; k = full HD=64)
    uint32_t qah[4][4], qal[4][4];
#pragma unroll
    for (int s = 0; s < 4; s++) {
        int o0 = rw * HP + s * 8 + tq;
        int o1 = (rw + 8) * HP + s * 8 + tq;
        qah[s][0] = qh[o0]; qah[s][1] = qh[o1];
        qah[s][2] = qh[o0 + 4]; qah[s][3] = qh[o1 + 4];
        qal[s][0] = ql[o0]; qal[s][1] = ql[o1];
        qal[s][2] = ql[o0 + 4]; qal[s][3] = ql[o1 + 4];
    }

    float m_i[2] = {-1e30f, -1e30f}, l_i[2] = {0.f, 0.f};
    float o[8][4] = {};

    const int nkt = 2 * qi + 2;
    for (int kt = 0; kt < nkt; kt++) {
        __syncthreads();
        // ---- stage K [64 keys][32 pairs] (coalesced) ----
        {
            const uint32_t* kph = kh + (size_t)kt * 64 * HP;
            const uint32_t* kpl = kl + (size_t)kt * 64 * HP;
#pragma unroll
            for (int it = 0; it < 8; it++) {
                int s = tid + it * 256;
                int key = s >> 5, pr = s & 31;
                Ksh[key * FP + pr] = kph[key * HP + pr];
                Ksl[key * FP + pr] = kpl[key * HP + pr];
            }
        }
        // ---- stage V transposed: Vt[hd][keypair] ----
        {
            const uint32_t* vph = vh + (size_t)kt * 64 * HP;
            const uint32_t* vpl = vl + (size_t)kt * 64 * HP;
#pragma unroll
            for (int it = 0; it < 8; it++) {
                int s = tid + it * 256;
                int key = s >> 5, j = s & 31;   // j = d-pair
                uint32_t wv = vph[key * HP + j];
                ((uint16_t*)Vth)[(2 * j) * (2 * FP) + key]     = (uint16_t)(wv & 0xffff);
                ((uint16_t*)Vth)[(2 * j + 1) * (2 * FP) + key] = (uint16_t)(wv >> 16);
                uint32_t wl = vpl[key * HP + j];
                ((uint16_t*)Vtl)[(2 * j) * (2 * FP) + key]     = (uint16_t)(wl & 0xffff);
                ((uint16_t*)Vtl)[(2 * j + 1) * (2 * FP) + key] = (uint16_t)(wl >> 16);
            }
        }
        __syncthreads();

        // Warp fully masked in this tile? (all cols > all its rows)
        if (q0 + warp * 16 + 15 < kt * 64) continue;

        // ---- S = Q K^T : 8 n8-tiles over 64 keys ----
        float s[8][4];
#pragma unroll
        for (int nt = 0; nt < 8; nt++) {
            float sa[4] = {};
#pragma unroll
            for (int ks = 0; ks < 4; ks++) {
                int ob = (nt * 8 + g) * FP + ks * 8 + tq;
                uint32_t bh2[2] = {Ksh[ob], Ksh[ob + 4]};
                uint32_t bl2[2] = {Ksl[ob], Ksl[ob + 4]};
                mma_bf16(sa, qah[ks], bl2);
                mma_bf16(sa, qal[ks], bh2);
                mma_bf16(sa, qah[ks], bh2);
            }
            s[nt][0] = sa[0]; s[nt][1] = sa[1]; s[nt][2] = sa[2]; s[nt][3] = sa[3];
        }

        // ---- scale + causal mask (only last two tiles can intersect diag) ----
        const bool need_mask = (kt >= 2 * qi);
#pragma unroll
        for (int nt = 0; nt < 8; nt++) {
            int c0 = kt * 64 + nt * 8 + 2 * tq;
#pragma unroll
            for (int r = 0; r < 4; r++) {
                int col = c0 + (r & 1);
                int row = rw + (r >> 1) * 8;
                float v = s[nt][r] * 0.125f;
                if (need_mask && col > row) v = -1e30f;
                s[nt][r] = v;
            }
        }

        // ---- online softmax (rows rw / rw+8; quad = 4 lanes share a row) ----
        float sc[2];
#pragma unroll
        for (int r = 0; r < 2; r++) {
            float mx = -1e30f;
#pragma unroll
            for (int nt = 0; nt < 8; nt++)
                mx = fmaxf(mx, fmaxf(s[nt][2 * r], s[nt][2 * r + 1]));
            mx = fmaxf(mx, __shfl_xor_sync(0xffffffffu, mx, 1));
            mx = fmaxf(mx, __shfl_xor_sync(0xffffffffu, mx, 2));
            float m_new = fmaxf(m_i[r], mx);
            float sum = 0.f;
#pragma unroll
            for (int nt = 0; nt < 8; nt++) {
                float p0 = __expf(s[nt][2 * r] - m_new);
                float p1 = __expf(s[nt][2 * r + 1] - m_new);
                s[nt][2 * r] = p0; s[nt][2 * r + 1] = p1;
                sum += p0 + p1;
            }
            sum += __shfl_xor_sync(0xffffffffu, sum, 1);
            sum += __shfl_xor_sync(0xffffffffu, sum, 2);
            sc[r]  = __expf(m_i[r] - m_new);
            l_i[r] = l_i[r] * sc[r] + sum;
            m_i[r] = m_new;
        }
#pragma unroll
        for (int nt = 0; nt < 8; nt++) {
            o[nt][0] *= sc[0]; o[nt][1] *= sc[0];
            o[nt][2] *= sc[1]; o[nt][3] *= sc[1];
        }

        // ---- PV: P fragments built in-register from S accums ----
#pragma unroll
        for (int ks = 0; ks < 4; ks++) {
            float ph[8], pl[8];
#pragma unroll
            for (int e = 0; e < 4; e++) {
                split2(s[2 * ks][e], ph[e], pl[e]);
                split2(s[2 * ks + 1][e], ph[4 + e], pl[4 + e]);
            }
            uint32_t pah[4] = { pack_bf16(ph[0], ph[1]), pack_bf16(ph[2], ph[3]),
                                pack_bf16(ph[4], ph[5]), pack_bf16(ph[6], ph[7]) };
            uint32_t pal[4] = { pack_bf16(pl[0], pl[1]), pack_bf16(pl[2], pl[3]),
                                pack_bf16(pl[4], pl[5]), pack_bf16(pl[6], pl[7]) };
#pragma unroll
            for (int nt = 0; nt < 8; nt++) {
                int ob = (nt * 8 + g) * FP + ks * 8 + tq;
                uint32_t bh2[2] = {Vth[ob], Vth[ob + 4]};
                uint32_t bl2[2] = {Vtl[ob], Vtl[ob + 4]};
                mma_bf16(o[nt], pah, bl2);
                mma_bf16(o[nt], pal, bh2);
                mma_bf16(o[nt], pah, bh2);
            }
        }
    }

    // ---- epilogue: o / l -> g_y [B,T,C] ----
    const int b = bh >> 4, h = bh & 15;
    float inv0 = 1.f / l_i[0], inv1 = 1.f / l_i[1];
#pragma unroll
    for (int nt = 0; nt < 8; nt++) {
        int d = h * HD + nt * 8 + 2 * tq;
        *(float2*)(g_y + (size_t)(b * NT + rw) * NC + d) =
            make_float2(o[nt][0] * inv0, o[nt][1] * inv0);
        *(float2*)(g_y + (size_t)(b * NT + rw + 8) * NC + d) =
            make_float2(o[nt][2] * inv1, o[nt][3] * inv1);
    }
}

// ===========================================================================
extern "C" void kernel_launch(void* const* d_in, const int* in_sizes, int n_in,
                              void* d_out, int out_size)
{
    const float* x      = (const float*)d_in[0];
    const float* w_attn = (const float*)d_in[1];
    const float* b_attn = (const float*)d_in[2];
    const float* w_proj = (const float*)d_in[3];
    const float* b_proj = (const float*)d_in[4];
    float* out = (float*)d_out;

    dim3 g1(3 * NC / BN, (NB * NT) / BM);   // (24, 64)
    gemm_bf16_kernel<0, 3 * NC><<<g1, 256>>>(x, w_attn, b_attn, nullptr);

    dim3 g2(NT / 128, NB * NHH);            // (16, 64)
    flash_mma_kernel<<<g2, 256>>>();

    dim3 g3(NC / BN, (NB * NT) / BM);       // (8, 64)
    gemm_bf16_kernel<1, NC><<<g3, 256>>>(nullptr, w_proj, b_proj, out);
}

// round 7
// speedup vs baseline: 2.8206x; 1.3433x over previous
#include <cuda_runtime.h>
#include <cuda_bf16.h>
#include <cstdint>
#include <math.h>

#define NB  4
#define NT  2048
#define NC  1024
#define NHH 16
#define HD  64
#define HP  32   // HD/2 packed u32 per row

// Device-global scratch (no cudaMalloc allowed)
__device__ uint32_t g_qh[(size_t)NB * NHH * NT * HP];
__device__ uint32_t g_ql[(size_t)NB * NHH * NT * HP];
__device__ uint32_t g_kh[(size_t)NB * NHH * NT * HP];
__device__ uint32_t g_kl[(size_t)NB * NHH * NT * HP];
__device__ uint32_t g_vh[(size_t)NB * NHH * NT * HP];
__device__ uint32_t g_vl[(size_t)NB * NHH * NT * HP];
__device__ float    g_y [(size_t)NB * NT * NC];

// ============================ helpers ============================
__device__ __forceinline__ uint32_t pack_bf16(float a, float b) {
    __nv_bfloat162 t = __floats2bfloat162_rn(a, b);
    return *(uint32_t*)&t;
}
__device__ __forceinline__ void split2(float x, float& hi, float& lo) {
    __nv_bfloat16 h = __float2bfloat16(x);
    hi = __bfloat162float(h);
    lo = x - hi;
}
__device__ __forceinline__ void mma_bf16(float* d, const uint32_t* a, const uint32_t* b) {
    asm volatile(
        "mma.sync.aligned.m16n8k16.row.col.f32.bf16.bf16.f32 "
        "{%0,%1,%2,%3}, {%4,%5,%6,%7}, {%8,%9}, {%0,%1,%2,%3};"
        : "+f"(d[0]), "+f"(d[1]), "+f"(d[2]), "+f"(d[3])
        : "r"(a[0]), "r"(a[1]), "r"(a[2]), "r"(a[3]), "r"(b[0]), "r"(b[1]));
}

// ===================== bf16x3 split mma.sync GEMM (pipelined) =====================
static constexpr int BM = 128, BN = 128, BK = 32;
static constexpr int KTOT = 1024, NCHUNK = KTOT / BK;
static constexpr int LDP = 20;
// dynamic smem stage layout (u32): As_hi 0 | As_lo 2560 | Bs_hi 5120 | Bs_lo 7680
static constexpr int G_STG = 10240;                   // u32 per stage
static constexpr int G_SMEM_BYTES = 2 * G_STG * 4;    // 81920

template <int MODE, int NGLOB>
__global__ __launch_bounds__(256) void gemm_bf16_kernel(
    const float* __restrict__ A, const float* __restrict__ W,
    const float* __restrict__ bias, float* __restrict__ out)
{
    extern __shared__ uint32_t dsm[];

    const int tid  = threadIdx.x;
    const int warp = tid >> 5, lane = tid & 31;
    const int g = lane >> 2, tq = lane & 3;
    const int wm = (warp >> 2) * 64;
    const int wn = (warp & 3) * 32;
    const int m0 = blockIdx.y * BM, n0 = blockIdx.x * BN;
    const float* __restrict__ Ap = (MODE == 0) ? A : (const float*)g_y;

    const int sn = tid & 127;
    const int pbase = (tid >> 7) * 8;
    const int arow = tid >> 1, ac4 = (tid & 1) * 2;   // A: 2 float4 per thread/row-half

    float4 pa[4];        // prefetched A (4 float4 = rows arow staged over its)
    float  pb[16];       // prefetched B

    // prefetch chunk ci into registers
    auto ldg_chunk = [&](int ci) {
        const int k0 = ci * BK;
#pragma unroll
        for (int it = 0; it < 4; it++) {
            int s = tid + it * 256;
            int row = s >> 3, q = s & 7;
            pa[it] = *(const float4*)(Ap + (size_t)(m0 + row) * KTOT + k0 + q * 4);
        }
        const float* wp = W + (size_t)(k0 + pbase * 2) * NGLOB + n0 + sn;
#pragma unroll
        for (int j = 0; j < 8; j++) {
            pb[2 * j]     = wp[0];
            pb[2 * j + 1] = wp[NGLOB];
            wp += 2 * (size_t)NGLOB;
        }
    };
    // convert + store prefetched regs into stage st
    auto sts_chunk = [&](uint32_t* st) {
        uint32_t* As_hi = st;
        uint32_t* As_lo = st + 2560;
        uint32_t* Bs_hi = st + 5120;
        uint32_t* Bs_lo = st + 7680;
#pragma unroll
        for (int it = 0; it < 4; it++) {
            int s = tid + it * 256;
            int row = s >> 3, q = s & 7;
            float h0, l0, h1, l1, h2, l2, h3, l3;
            split2(pa[it].x, h0, l0); split2(pa[it].y, h1, l1);
            split2(pa[it].z, h2, l2); split2(pa[it].w, h3, l3);
            int o = row * LDP + q * 2;
            As_hi[o]     = pack_bf16(h0, h1);
            As_hi[o + 1] = pack_bf16(h2, h3);
            As_lo[o]     = pack_bf16(l0, l1);
            As_lo[o + 1] = pack_bf16(l2, l3);
        }
#pragma unroll
        for (int j = 0; j < 8; j++) {
            float h0, l0, h1, l1;
            split2(pb[2 * j], h0, l0); split2(pb[2 * j + 1], h1, l1);
            Bs_hi[sn * LDP + pbase + j] = pack_bf16(h0, h1);
            Bs_lo[sn * LDP + pbase + j] = pack_bf16(l0, l1);
        }
    };

    float acc[4][4][4] = {};

    ldg_chunk(0);
    sts_chunk(dsm);
    __syncthreads();

    for (int ci = 0; ci < NCHUNK; ci++) {
        if (ci + 1 < NCHUNK) ldg_chunk(ci + 1);

        uint32_t* st = dsm + (ci & 1) * G_STG;
        const uint32_t* As_hi = st;
        const uint32_t* As_lo = st + 2560;
        const uint32_t* Bs_hi = st + 5120;
        const uint32_t* Bs_lo = st + 7680;
#pragma unroll
        for (int ks = 0; ks < 2; ks++) {
            const int pb2 = ks * 8 + tq;
            uint32_t ah[4][4], al[4][4];
#pragma unroll
            for (int fm = 0; fm < 4; fm++) {
                int r0 = (wm + fm * 16 + g) * LDP + pb2;
                int r1 = r0 + 8 * LDP;
                ah[fm][0] = As_hi[r0];     ah[fm][1] = As_hi[r1];
                ah[fm][2] = As_hi[r0 + 4]; ah[fm][3] = As_hi[r1 + 4];
                al[fm][0] = As_lo[r0];     al[fm][1] = As_lo[r1];
                al[fm][2] = As_lo[r0 + 4]; al[fm][3] = As_lo[r1 + 4];
            }
            uint32_t bh[4][2], bl[4][2];
#pragma unroll
            for (int fn = 0; fn < 4; fn++) {
                int o = (wn + fn * 8 + g) * LDP + pb2;
                bh[fn][0] = Bs_hi[o]; bh[fn][1] = Bs_hi[o + 4];
                bl[fn][0] = Bs_lo[o]; bl[fn][1] = Bs_lo[o + 4];
            }
#pragma unroll
            for (int fm = 0; fm < 4; fm++)
#pragma unroll
                for (int fn = 0; fn < 4; fn++) {
                    mma_bf16(acc[fm][fn], ah[fm], bl[fn]);
                    mma_bf16(acc[fm][fn], al[fm], bh[fn]);
                    mma_bf16(acc[fm][fn], ah[fm], bh[fn]);
                }
        }

        if (ci + 1 < NCHUNK) sts_chunk(dsm + ((ci + 1) & 1) * G_STG);
        __syncthreads();
    }

    // ---- epilogue ----
#pragma unroll
    for (int fm = 0; fm < 4; fm++) {
#pragma unroll
        for (int fn = 0; fn < 4; fn++) {
            int ng = n0 + wn + fn * 8 + tq * 2;
#pragma unroll
            for (int half = 0; half < 2; half++) {
                int m = m0 + wm + fm * 16 + g + half * 8;
                float v0 = acc[fm][fn][half * 2 + 0] + bias[ng];
                float v1 = acc[fm][fn][half * 2 + 1] + bias[ng + 1];
                if (MODE == 0) {
                    const int which = ng >> 10;
                    const int h = (ng & (NC - 1)) >> 6;
                    const int d = ng & (HD - 1);
                    float h0, l0, h1, l1;
                    split2(v0, h0, l0); split2(v1, h1, l1);
                    size_t idx = (((size_t)(m >> 11) * NHH + h) * NT + (m & (NT - 1))) * HP + (d >> 1);
                    uint32_t* dh = (which == 0) ? g_qh : (which == 1) ? g_kh : g_vh;
                    uint32_t* dl = (which == 0) ? g_ql : (which == 1) ? g_kl : g_vl;
                    dh[idx] = pack_bf16(h0, h1);
                    dl[idx] = pack_bf16(l0, l1);
                } else {
                    *(float2*)(out + (size_t)m * NGLOB + ng) = make_float2(v0, v1);
                }
            }
        }
    }
}

// ===================== flash attention, mma.sync bf16x3 (pipelined) =====================
static constexpr int FP = 36;
// stage layout (u32): Ksh 0 | Ksl 2304 | Vth 4608 | Vtl 6912 ; stage = 9216 u32
static constexpr int F_STG = 9216;
static constexpr int F_SMEM_BYTES = 2 * F_STG * 4;    // 73728

__global__ __launch_bounds__(256) void flash_mma_kernel()
{
    extern __shared__ uint32_t fsm[];

    const int tid  = threadIdx.x;
    const int warp = tid >> 5, lane = tid & 31;
    const int g = lane >> 2, tq = lane & 3;
    const int qi = blockIdx.x, bh = blockIdx.y;
    const int q0 = qi * 128;
    const int rw = q0 + warp * 16 + g;

    const size_t base = (size_t)bh * NT * HP;
    const uint32_t* __restrict__ qh = g_qh + base;
    const uint32_t* __restrict__ ql = g_ql + base;
    const uint32_t* __restrict__ kh = g_kh + base;
    const uint32_t* __restrict__ kl = g_kl + base;
    const uint32_t* __restrict__ vh = g_vh + base;
    const uint32_t* __restrict__ vl = g_vl + base;

    const int skey = tid >> 5;           // staging: this thread's key row stride base
    const int spr  = tid & 31;

    uint32_t krh[8], krl[8], vrh[8], vrl[8];   // prefetched K/V tile

    auto ldg_tile = [&](int kt) {
        const uint32_t* kph = kh + (size_t)kt * 64 * HP;
        const uint32_t* kpl = kl + (size_t)kt * 64 * HP;
        const uint32_t* vph = vh + (size_t)kt * 64 * HP;
        const uint32_t* vpl = vl + (size_t)kt * 64 * HP;
#pragma unroll
        for (int it = 0; it < 8; it++) {
            int key = skey + it * 8;
            krh[it] = kph[key * HP + spr];
            krl[it] = kpl[key * HP + spr];
            vrh[it] = vph[key * HP + spr];
            vrl[it] = vpl[key * HP + spr];
        }
    };
    auto sts_tile = [&](uint32_t* st) {
        uint32_t* Ksh = st;
        uint32_t* Ksl = st + 2304;
        uint16_t* Vth = (uint16_t*)(st + 4608);
        uint16_t* Vtl = (uint16_t*)(st + 6912);
#pragma unroll
        for (int it = 0; it < 8; it++) {
            int key = skey + it * 8;
            Ksh[key * FP + spr] = krh[it];
            Ksl[key * FP + spr] = krl[it];
            int j = spr;   // d-pair
            Vth[(2 * j) * (2 * FP) + key]     = (uint16_t)(vrh[it] & 0xffff);
            Vth[(2 * j + 1) * (2 * FP) + key] = (uint16_t)(vrh[it] >> 16);
            Vtl[(2 * j) * (2 * FP) + key]     = (uint16_t)(vrl[it] & 0xffff);
            Vtl[(2 * j + 1) * (2 * FP) + key] = (uint16_t)(vrl[it] >> 16);
        }
    };

    // Q fragments (rows rw, rw+8; full HD)
    uint32_t qah[4][4], qal[4][4];
#pragma unroll
    for (int s = 0; s < 4; s++) {
        int o0 = rw * HP + s * 8 + tq;
        int o1 = (rw + 8) * HP + s * 8 + tq;
        qah[s][0] = qh[o0]; qah[s][1] = qh[o1];
        qah[s][2] = qh[o0 + 4]; qah[s][3] = qh[o1 + 4];
        qal[s][0] = ql[o0]; qal[s][1] = ql[o1];
        qal[s][2] = ql[o0 + 4]; qal[s][3] = ql[o1 + 4];
    }

    float m_i[2] = {-1e30f, -1e30f}, l_i[2] = {0.f, 0.f};
    float o[8][4] = {};

    const int nkt = 2 * qi + 2;
    ldg_tile(0);
    sts_tile(fsm);
    __syncthreads();

    for (int kt = 0; kt < nkt; kt++) {
        if (kt + 1 < nkt) ldg_tile(kt + 1);

        // compute (skip if this warp fully masked in tile kt)
        if (q0 + warp * 16 + 15 >= kt * 64) {
            uint32_t* st = fsm + (kt & 1) * F_STG;
            const uint32_t* Ksh = st;
            const uint32_t* Ksl = st + 2304;
            const uint32_t* Vth = st + 4608;
            const uint32_t* Vtl = st + 6912;

            float s[8][4];
#pragma unroll
            for (int nt = 0; nt < 8; nt++) {
                float sa[4] = {};
#pragma unroll
                for (int ks = 0; ks < 4; ks++) {
                    int ob = (nt * 8 + g) * FP + ks * 8 + tq;
                    uint32_t bh2[2] = {Ksh[ob], Ksh[ob + 4]};
                    uint32_t bl2[2] = {Ksl[ob], Ksl[ob + 4]};
                    mma_bf16(sa, qah[ks], bl2);
                    mma_bf16(sa, qal[ks], bh2);
                    mma_bf16(sa, qah[ks], bh2);
                }
                s[nt][0] = sa[0]; s[nt][1] = sa[1]; s[nt][2] = sa[2]; s[nt][3] = sa[3];
            }

            const bool need_mask = (kt >= 2 * qi);
#pragma unroll
            for (int nt = 0; nt < 8; nt++) {
                int c0 = kt * 64 + nt * 8 + 2 * tq;
#pragma unroll
                for (int r = 0; r < 4; r++) {
                    int col = c0 + (r & 1);
                    int row = rw + (r >> 1) * 8;
                    float v = s[nt][r] * 0.125f;
                    if (need_mask && col > row) v = -1e30f;
                    s[nt][r] = v;
                }
            }

            float sc[2];
#pragma unroll
            for (int r = 0; r < 2; r++) {
                float mx = -1e30f;
#pragma unroll
                for (int nt = 0; nt < 8; nt++)
                    mx = fmaxf(mx, fmaxf(s[nt][2 * r], s[nt][2 * r + 1]));
                mx = fmaxf(mx, __shfl_xor_sync(0xffffffffu, mx, 1));
                mx = fmaxf(mx, __shfl_xor_sync(0xffffffffu, mx, 2));
                float m_new = fmaxf(m_i[r], mx);
                float sum = 0.f;
#pragma unroll
                for (int nt = 0; nt < 8; nt++) {
                    float p0 = __expf(s[nt][2 * r] - m_new);
                    float p1 = __expf(s[nt][2 * r + 1] - m_new);
                    s[nt][2 * r] = p0; s[nt][2 * r + 1] = p1;
                    sum += p0 + p1;
                }
                sum += __shfl_xor_sync(0xffffffffu, sum, 1);
                sum += __shfl_xor_sync(0xffffffffu, sum, 2);
                sc[r]  = __expf(m_i[r] - m_new);
                l_i[r] = l_i[r] * sc[r] + sum;
                m_i[r] = m_new;
            }
#pragma unroll
            for (int nt = 0; nt < 8; nt++) {
                o[nt][0] *= sc[0]; o[nt][1] *= sc[0];
                o[nt][2] *= sc[1]; o[nt][3] *= sc[1];
            }

#pragma unroll
            for (int ks = 0; ks < 4; ks++) {
                float ph[8], pl[8];
#pragma unroll
                for (int e = 0; e < 4; e++) {
                    split2(s[2 * ks][e], ph[e], pl[e]);
                    split2(s[2 * ks + 1][e], ph[4 + e], pl[4 + e]);
                }
                uint32_t pah[4] = { pack_bf16(ph[0], ph[1]), pack_bf16(ph[2], ph[3]),
                                    pack_bf16(ph[4], ph[5]), pack_bf16(ph[6], ph[7]) };
                uint32_t pal[4] = { pack_bf16(pl[0], pl[1]), pack_bf16(pl[2], pl[3]),
                                    pack_bf16(pl[4], pl[5]), pack_bf16(pl[6], pl[7]) };
#pragma unroll
                for (int nt = 0; nt < 8; nt++) {
                    int ob = (nt * 8 + g) * FP + ks * 8 + tq;
                    uint32_t bh2[2] = {Vth[ob], Vth[ob + 4]};
                    uint32_t bl2[2] = {Vtl[ob], Vtl[ob + 4]};
                    mma_bf16(o[nt], pah, bl2);
                    mma_bf16(o[nt], pal, bh2);
                    mma_bf16(o[nt], pah, bh2);
                }
            }
        }

        if (kt + 1 < nkt) sts_tile(fsm + ((kt + 1) & 1) * F_STG);
        __syncthreads();
    }

    // ---- epilogue ----
    const int b = bh >> 4, h = bh & 15;
    float inv0 = 1.f / l_i[0], inv1 = 1.f / l_i[1];
#pragma unroll
    for (int nt = 0; nt < 8; nt++) {
        int d = h * HD + nt * 8 + 2 * tq;
        *(float2*)(g_y + (size_t)(b * NT + rw) * NC + d) =
            make_float2(o[nt][0] * inv0, o[nt][1] * inv0);
        *(float2*)(g_y + (size_t)(b * NT + rw + 8) * NC + d) =
            make_float2(o[nt][2] * inv1, o[nt][3] * inv1);
    }
}

// ===========================================================================
extern "C" void kernel_launch(void* const* d_in, const int* in_sizes, int n_in,
                              void* d_out, int out_size)
{
    const float* x      = (const float*)d_in[0];
    const float* w_attn = (const float*)d_in[1];
    const float* b_attn = (const float*)d_in[2];
    const float* w_proj = (const float*)d_in[3];
    const float* b_proj = (const float*)d_in[4];
    float* out = (float*)d_out;

    cudaFuncSetAttribute(gemm_bf16_kernel<0, 3 * NC>,
                         cudaFuncAttributeMaxDynamicSharedMemorySize, G_SMEM_BYTES);
    cudaFuncSetAttribute(gemm_bf16_kernel<1, NC>,
                         cudaFuncAttributeMaxDynamicSharedMemorySize, G_SMEM_BYTES);
    cudaFuncSetAttribute(flash_mma_kernel,
                         cudaFuncAttributeMaxDynamicSharedMemorySize, F_SMEM_BYTES);

    dim3 g1(3 * NC / BN, (NB * NT) / BM);   // (24, 64)
    gemm_bf16_kernel<0, 3 * NC><<<g1, 256, G_SMEM_BYTES>>>(x, w_attn, b_attn, nullptr);

    dim3 g2(NT / 128, NB * NHH);            // (16, 64)
    flash_mma_kernel<<<g2, 256, F_SMEM_BYTES>>>();

    dim3 g3(NC / BN, (NB * NT) / BM);       // (8, 64)
    gemm_bf16_kernel<1, NC><<<g3, 256, G_SMEM_BYTES>>>(nullptr, w_proj, b_proj, out);
}